// round 6
// baseline (speedup 1.0000x reference)
#include <cuda_runtime.h>
#include <cstdint>

#define C 128
#define KC 27
#define NLOW_MAX 50000
#define E_MAX 1000000
#define EPAD_MAX (E_MAX + KC * 128)
#define MAXBLK 2048

// Packed per-row tf32 layout: row r, word  tg*32 + q*4 + w  holds col c = 16q + 4w + tg
__device__ unsigned g_xr[(size_t)NLOW_MAX * C];      // 25.6 MB
__device__ unsigned g_wr[(size_t)KC * C * C];        // 1.77 MB

__device__ int g_js[EPAD_MAX];
__device__ int g_is[EPAD_MAX];
__device__ int g_cnt[KC];
__device__ int g_cursor[KC];
__device__ int g_poffs[KC];
__device__ int g_blk_k[MAXBLK];
__device__ int g_blk_c0[MAXBLK];
__device__ int g_blk_nc[MAXBLK];
__device__ int g_nblocks;

__device__ __forceinline__ unsigned f2tf32(float x) {
    unsigned u;
    asm("cvt.rna.tf32.f32 %0, %1;" : "=r"(u) : "f"(x));
    return u;
}

__device__ __forceinline__ void mma_tf32(float c[4],
                                         unsigned a0, unsigned a1, unsigned a2, unsigned a3,
                                         unsigned b0, unsigned b1) {
    asm volatile(
        "mma.sync.aligned.m16n8k8.row.col.f32.tf32.tf32.f32 "
        "{%0,%1,%2,%3}, {%4,%5,%6,%7}, {%8,%9}, {%0,%1,%2,%3};\n"
        : "+f"(c[0]), "+f"(c[1]), "+f"(c[2]), "+f"(c[3])
        : "r"(a0), "r"(a1), "r"(a2), "r"(a3), "r"(b0), "r"(b1));
}

__device__ __forceinline__ void cpa16(unsigned saddr, const void* gptr) {
    asm volatile("cp.async.cg.shared.global [%0], [%1], 16;"
                 :: "r"(saddr), "l"(gptr) : "memory");
}

// ---- pre-pass: X rows -> packed tf32 ----
__global__ void pack_x_kernel(const float* __restrict__ X, int N) {
    int idx = blockIdx.x * blockDim.x + threadIdx.x;     // one float4 per thread
    if (idx >= N * 32) return;
    int row = idx >> 5;
    int c0 = (idx & 31) << 2;
    float4 f = *(const float4*)(X + (size_t)row * C + c0);
    int w = (c0 >> 2) & 3, q = c0 >> 4;
    unsigned* dst = g_xr + (size_t)row * C + q * 4 + w;
    dst[0]  = f2tf32(f.x);
    dst[32] = f2tf32(f.y);
    dst[64] = f2tf32(f.z);
    dst[96] = f2tf32(f.w);
}

__global__ void pack_w_kernel(const float* __restrict__ W) {
    int idx = blockIdx.x * blockDim.x + threadIdx.x;
    if (idx >= KC * 128 * 32) return;
    int c0 = (idx & 31) << 2;
    int row = idx >> 5;                    // k*128 + co
    float4 f = *(const float4*)(W + (size_t)row * C + c0);
    int w = (c0 >> 2) & 3, q = c0 >> 4;
    unsigned* dst = g_wr + (size_t)row * C + q * 4 + w;
    dst[0]  = f2tf32(f.x);
    dst[32] = f2tf32(f.y);
    dst[64] = f2tf32(f.z);
    dst[96] = f2tf32(f.w);
}

// ---- sort by k: init pads / histogram / offsets / scatter ----
__global__ void init_pad_kernel(int epad) {
    int idx = blockIdx.x * blockDim.x + threadIdx.x;
    if (idx < epad) { g_js[idx] = 0; g_is[idx] = -1; }
    if (idx < KC) g_cnt[idx] = 0;
}

__global__ void hist_kernel(const int* __restrict__ kc, int E) {
    __shared__ int h[KC];
    int tid = threadIdx.x;
    if (tid < KC) h[tid] = 0;
    __syncthreads();
    for (int e = blockIdx.x * blockDim.x + tid; e < E; e += gridDim.x * blockDim.x)
        atomicAdd(&h[kc[e]], 1);
    __syncthreads();
    if (tid < KC) atomicAdd(&g_cnt[tid], h[tid]);
}

__global__ void offsets_kernel() {
    if (threadIdx.x != 0) return;
    int off = 0, nb = 0;
    for (int k = 0; k < KC; k++) {
        g_poffs[k] = off;
        g_cursor[k] = off;
        int ch = (g_cnt[k] + 127) >> 7;
        off += ch << 7;
        for (int q = 0; q < ch; q += 4) {
            g_blk_k[nb] = k;
            g_blk_c0[nb] = q;
            g_blk_nc[nb] = (ch - q) < 4 ? (ch - q) : 4;
            nb++;
        }
    }
    g_nblocks = nb;
}

__global__ void sort_kernel(const int* __restrict__ ih, const int* __restrict__ jl,
                            const int* __restrict__ kc, int E) {
    int e = blockIdx.x * blockDim.x + threadIdx.x;
    if (e >= E) return;
    int k = kc[e];
    int pos = atomicAdd(&g_cursor[k], 1);
    g_js[pos] = jl[e];
    g_is[pos] = ih[e];
}

// out[n][c] = bias[c]
__global__ void init_out_kernel(float* __restrict__ out, const float* __restrict__ bias,
                                int total4) {
    int idx = blockIdx.x * blockDim.x + threadIdx.x;
    if (idx < total4) {
        float4 b = ((const float4*)bias)[idx & 31];
        ((float4*)out)[idx] = b;
    }
}

// ---- fused gather-GEMM-scatter ----
// smem tile layout: row stride 144 words, tg stride 36 (conflict-free LDS.128)
#define ROW_STR 144
#define TG_STR 36
#define TILE_WORDS (128 * ROW_STR)
#define ACC_STR 136                   // acc staging stride (conflict-free STS.64 / LDS.128)
#define SMEM_BYTES (3 * TILE_WORDS * 4)   // 221,184 B

__device__ __forceinline__ void stage_A(unsigned sbuf, int base, int tid) {
    int r = tid >> 2;                 // 4 threads per row
    int sub = tid & 3;                // = tg
    int j = g_js[base + r];
    const unsigned* src = g_xr + (size_t)j * C + sub * 32;
    unsigned dst = sbuf + (r * ROW_STR + sub * TG_STR) * 4;
#pragma unroll
    for (int q = 0; q < 8; q++)
        cpa16(dst + q * 16, src + q * 4);
}

__global__ void __launch_bounds__(512, 1) fused_kernel(float* __restrict__ out, int N) {
    int b = blockIdx.x;
    if (b >= g_nblocks) return;
    extern __shared__ unsigned smem[];
    unsigned* Ws = smem;
    unsigned* Ab[2] = { smem + TILE_WORDS, smem + 2 * TILE_WORDS };
    const int tid = threadIdx.x;

    const int k   = g_blk_k[b];
    const int c0  = g_blk_c0[b];
    const int nc  = g_blk_nc[b];
    const int pb  = g_poffs[k];

    unsigned sW = (unsigned)__cvta_generic_to_shared(Ws);
    unsigned sA[2] = { (unsigned)__cvta_generic_to_shared(Ab[0]),
                       (unsigned)__cvta_generic_to_shared(Ab[1]) };

    // G0: W + A(chunk 0)
    {
        const unsigned* wsrc = g_wr + (size_t)k * C * C;
#pragma unroll
        for (int i = 0; i < 8; i++) {
            int cidx = tid + i * 512;
            int row = cidx >> 5, u = cidx & 31;
            int tg = u >> 3, q = u & 7;
            cpa16(sW + (row * ROW_STR + tg * TG_STR + q * 4) * 4,
                  wsrc + row * C + tg * 32 + q * 4);
        }
        stage_A(sA[0], pb + (c0 + 0) * 128, tid);
    }
    asm volatile("cp.async.commit_group;");
    // G1: A(chunk 1) (or empty)
    if (nc > 1) stage_A(sA[1], pb + (c0 + 1) * 128, tid);
    asm volatile("cp.async.commit_group;");

    const int warp = tid >> 5, lane = tid & 31;
    const int g = lane >> 2, tg = lane & 3;
    const int rowBase = (warp >> 2) * 32;
    const int coBase  = (warp & 3) * 32;
    const int bOff = (coBase + g) * ROW_STR + tg * TG_STR;
    const int ntStride = (8 * ROW_STR) / 4;

    for (int t = 0; t < nc; t++) {
        asm volatile("cp.async.wait_group 1;" ::: "memory");
        __syncthreads();

        unsigned* Ax = Ab[t & 1];
        const uint4* A0 = (const uint4*)(Ax + (rowBase + g     ) * ROW_STR + tg * TG_STR);
        const uint4* A1 = (const uint4*)(Ax + (rowBase + g +  8) * ROW_STR + tg * TG_STR);
        const uint4* A2 = (const uint4*)(Ax + (rowBase + g + 16) * ROW_STR + tg * TG_STR);
        const uint4* A3 = (const uint4*)(Ax + (rowBase + g + 24) * ROW_STR + tg * TG_STR);
        const uint4* Bp = (const uint4*)(Ws + bOff);

        float acc[2][4][4];
#pragma unroll
        for (int mt = 0; mt < 2; mt++)
#pragma unroll
            for (int nt = 0; nt < 4; nt++) {
                acc[mt][nt][0] = 0.f; acc[mt][nt][1] = 0.f;
                acc[mt][nt][2] = 0.f; acc[mt][nt][3] = 0.f;
            }

#pragma unroll
        for (int q = 0; q < 8; q++) {
            uint4 a0 = A0[q];
            uint4 a1 = A1[q];
            uint4 a2 = A2[q];
            uint4 a3 = A3[q];
            uint4 b0 = Bp[0 * ntStride + q];
            uint4 b1 = Bp[1 * ntStride + q];
            uint4 b2 = Bp[2 * ntStride + q];
            uint4 b3 = Bp[3 * ntStride + q];
            mma_tf32(acc[0][0], a0.x, a1.x, a0.y, a1.y, b0.x, b0.y);
            mma_tf32(acc[0][1], a0.x, a1.x, a0.y, a1.y, b1.x, b1.y);
            mma_tf32(acc[0][2], a0.x, a1.x, a0.y, a1.y, b2.x, b2.y);
            mma_tf32(acc[0][3], a0.x, a1.x, a0.y, a1.y, b3.x, b3.y);
            mma_tf32(acc[1][0], a2.x, a3.x, a2.y, a3.y, b0.x, b0.y);
            mma_tf32(acc[1][1], a2.x, a3.x, a2.y, a3.y, b1.x, b1.y);
            mma_tf32(acc[1][2], a2.x, a3.x, a2.y, a3.y, b2.x, b2.y);
            mma_tf32(acc[1][3], a2.x, a3.x, a2.y, a3.y, b3.x, b3.y);
            mma_tf32(acc[0][0], a0.z, a1.z, a0.w, a1.w, b0.z, b0.w);
            mma_tf32(acc[0][1], a0.z, a1.z, a0.w, a1.w, b1.z, b1.w);
            mma_tf32(acc[0][2], a0.z, a1.z, a0.w, a1.w, b2.z, b2.w);
            mma_tf32(acc[0][3], a0.z, a1.z, a0.w, a1.w, b3.z, b3.w);
            mma_tf32(acc[1][0], a2.z, a3.z, a2.w, a3.w, b0.z, b0.w);
            mma_tf32(acc[1][1], a2.z, a3.z, a2.w, a3.w, b1.z, b1.w);
            mma_tf32(acc[1][2], a2.z, a3.z, a2.w, a3.w, b2.z, b2.w);
            mma_tf32(acc[1][3], a2.z, a3.z, a2.w, a3.w, b3.z, b3.w);
        }

        // stage acc into the A buffer we just finished reading
        __syncthreads();
        float* As = (float*)Ax;
#pragma unroll
        for (int mt = 0; mt < 2; mt++) {
            int r0 = rowBase + mt * 16 + g;
#pragma unroll
            for (int nt = 0; nt < 4; nt++) {
                int co = coBase + nt * 8 + tg * 2;
                *(float2*)(As + r0 * ACC_STR + co) =
                    make_float2(acc[mt][nt][0], acc[mt][nt][1]);
                *(float2*)(As + (r0 + 8) * ACC_STR + co) =
                    make_float2(acc[mt][nt][2], acc[mt][nt][3]);
            }
        }
        __syncthreads();

        // scatter: warp per row, red.v4 to out[i]
        int baseE = pb + (c0 + t) * 128;
#pragma unroll
        for (int rr = 0; rr < 8; rr++) {
            int row = warp * 8 + rr;
            int i = g_is[baseE + row];
            if (i >= 0) {
                float4 v = *(const float4*)(As + row * ACC_STR + lane * 4);
                float* dst = out + (size_t)i * C + lane * 4;
                asm volatile("red.global.add.v4.f32 [%0], {%1,%2,%3,%4};"
                             :: "l"(dst), "f"(v.x), "f"(v.y), "f"(v.z), "f"(v.w)
                             : "memory");
            }
        }
        __syncthreads();

        // prefetch chunk t+2 into this buffer
        if (t + 2 < nc) stage_A(sA[t & 1], pb + (c0 + t + 2) * 128, tid);
        asm volatile("cp.async.commit_group;");
    }
}

extern "C" void kernel_launch(void* const* d_in, const int* in_sizes, int n_in,
                              void* d_out, int out_size) {
    const float* x    = (const float*)d_in[0];
    const float* w    = (const float*)d_in[1];
    const float* bias = (const float*)d_in[2];
    const int* ih     = (const int*)d_in[3];
    const int* jl     = (const int*)d_in[4];
    const int* kc     = (const int*)d_in[5];
    float* out = (float*)d_out;

    const int Nlow = in_sizes[0] / C;
    const int E    = in_sizes[3];
    const int epad = E + KC * 128;

    pack_x_kernel<<<(Nlow * 32 + 255) / 256, 256>>>(x, Nlow);
    pack_w_kernel<<<(KC * 128 * 32 + 255) / 256, 256>>>(w);

    init_pad_kernel<<<(epad + 255) / 256, 256>>>(epad);
    hist_kernel<<<512, 256>>>(kc, E);
    offsets_kernel<<<1, 32>>>();
    sort_kernel<<<(E + 255) / 256, 256>>>(ih, jl, kc, E);

    int total4 = out_size / 4;
    init_out_kernel<<<(total4 + 255) / 256, 256>>>(out, bias, total4);

    cudaFuncSetAttribute(fused_kernel, cudaFuncAttributeMaxDynamicSharedMemorySize,
                         SMEM_BYTES);
    fused_kernel<<<MAXBLK, 512, SMEM_BYTES>>>(out, Nlow);
}